// round 2
// baseline (speedup 1.0000x reference)
#include <cuda_runtime.h>
#include <math.h>

#define BB   32
#define CC   256
#define HH   64
#define WWID 64
#define MIP  8
#define HID  256
#define OUTD 14

// Scratch (no allocations allowed)
__device__ float g_pool[BB * CC * 128];   // per (b,c): [0:64]=row means (xh), [64:128]=col means (xw)
__device__ float g_y[BB * MIP * 128];     // hswish(bn(ca_w1 @ pooled))
__device__ float g_p[BB * CC];            // gated pooled features

// ---------------------------------------------------------------------------
// Kernel 1: per-(b,c) 64x64 tile -> row means + col means. Fully coalesced.
// thread t owns float4 indices f = k*128 + t  (k=0..7):
//   h = f/16 = 8k + t/16,   w-group = 4*(t%16)
// ---------------------------------------------------------------------------
__global__ __launch_bounds__(128) void k_pool(const float* __restrict__ x) {
    int bid = blockIdx.x;
    int t = threadIdx.x;
    const float4* xp = reinterpret_cast<const float4*>(x) + (size_t)bid * 1024;

    float4 v[8];
#pragma unroll
    for (int k = 0; k < 8; k++) v[k] = xp[k * 128 + t];

    int sub = t >> 4;        // 0..7
    int lane16 = t & 15;     // 0..15

    __shared__ float srow[64];
    __shared__ float scol[8][64];

    float c0 = 0.f, c1 = 0.f, c2 = 0.f, c3 = 0.f;
#pragma unroll
    for (int k = 0; k < 8; k++) {
        float rp = v[k].x + v[k].y + v[k].z + v[k].w;
#pragma unroll
        for (int off = 8; off >= 1; off >>= 1)
            rp += __shfl_xor_sync(0xffffffffu, rp, off, 16);
        if (lane16 == 0) srow[k * 8 + sub] = rp;
        c0 += v[k].x; c1 += v[k].y; c2 += v[k].z; c3 += v[k].w;
    }
    scol[sub][lane16 * 4 + 0] = c0;
    scol[sub][lane16 * 4 + 1] = c1;
    scol[sub][lane16 * 4 + 2] = c2;
    scol[sub][lane16 * 4 + 3] = c3;
    __syncthreads();

    if (t < 64) {
        float cs = 0.f;
#pragma unroll
        for (int r = 0; r < 8; r++) cs += scol[r][t];
        float* outp = g_pool + (size_t)bid * 128;
        outp[t]      = srow[t] * (1.0f / 64.0f);   // xh[h] = mean over w
        outp[64 + t] = cs      * (1.0f / 64.0f);   // xw[w] = mean over h
    }
}

// ---------------------------------------------------------------------------
// Kernel 2: y[b,m,l] = hswish(bn(sum_c ca_w1[m,c] * pool[b,c,l])). 32 blocks.
// ---------------------------------------------------------------------------
__global__ __launch_bounds__(128) void k_y(
    const float* __restrict__ w1, const float* __restrict__ bg,
    const float* __restrict__ bb, const float* __restrict__ bm,
    const float* __restrict__ bv) {
    int b = blockIdx.x;
    int t = threadIdx.x;   // t = l (0..127)
    __shared__ float sw1[MIP][CC];
#pragma unroll
    for (int m = 0; m < MIP; m++) {
        sw1[m][t]       = w1[m * CC + t];
        sw1[m][t + 128] = w1[m * CC + t + 128];
    }
    __syncthreads();

    const float* pb = g_pool + (size_t)b * CC * 128;
    float acc[MIP];
#pragma unroll
    for (int m = 0; m < MIP; m++) acc[m] = 0.f;

    for (int c = 0; c < CC; c++) {
        float val = pb[c * 128 + t];
#pragma unroll
        for (int m = 0; m < MIP; m++) acc[m] = fmaf(sw1[m][c], val, acc[m]);
    }
#pragma unroll
    for (int m = 0; m < MIP; m++) {
        float scale = bg[m] * rsqrtf(bv[m] + 1e-5f);
        float yv = (acc[m] - bm[m]) * scale + bb[m];
        float hs = yv * fminf(fmaxf(yv + 3.0f, 0.0f), 6.0f) * (1.0f / 6.0f);
        g_y[(b * MIP + m) * 128 + t] = hs;
    }
}

// ---------------------------------------------------------------------------
// Kernel 3: gated pooling. One block per (b,c). Gates recomputed from g_y
// (cheap: 8 FMAs per gate, g_y is 128 KB and L2-resident).
// p[b,c] = (1/4096) * sum_h a_h[h] * sum_w x[h,w] * a_w[w]
// ---------------------------------------------------------------------------
__global__ __launch_bounds__(128) void k_wpool(
    const float* __restrict__ x, const float* __restrict__ wh,
    const float* __restrict__ ww) {
    int bid = blockIdx.x;
    int t = threadIdx.x;
    int b = bid >> 8;
    int c = bid & 255;

    const float4* xp = reinterpret_cast<const float4*>(x) + (size_t)bid * 1024;
    float4 v[8];
#pragma unroll
    for (int k = 0; k < 8; k++) v[k] = xp[k * 128 + t];

    __shared__ float sah[64];
    __shared__ float saw[64];
    const float* yb = g_y + (size_t)b * MIP * 128;

    if (t < 64) {
        float s = 0.f;
#pragma unroll
        for (int m = 0; m < MIP; m++) s = fmaf(wh[c * MIP + m], yb[m * 128 + t], s);
        sah[t] = 1.0f / (1.0f + expf(-s));
    } else {
        int w = t - 64;
        float s = 0.f;
#pragma unroll
        for (int m = 0; m < MIP; m++) s = fmaf(ww[c * MIP + m], yb[m * 128 + 64 + w], s);
        saw[w] = 1.0f / (1.0f + expf(-s));
    }
    __syncthreads();

    int sub = t >> 4, lane16 = t & 15, w0 = lane16 * 4;
    float acc = 0.f;
#pragma unroll
    for (int k = 0; k < 8; k++) {
        int h = k * 8 + sub;
        float rs = v[k].x * saw[w0] + v[k].y * saw[w0 + 1] +
                   v[k].z * saw[w0 + 2] + v[k].w * saw[w0 + 3];
        acc = fmaf(sah[h], rs, acc);
    }
#pragma unroll
    for (int off = 16; off >= 1; off >>= 1)
        acc += __shfl_xor_sync(0xffffffffu, acc, off);
    __shared__ float swr[4];
    if ((t & 31) == 0) swr[t >> 5] = acc;
    __syncthreads();
    if (t == 0) g_p[bid] = (swr[0] + swr[1] + swr[2] + swr[3]) * (1.0f / 4096.0f);
}

// ---------------------------------------------------------------------------
// Geometry helpers (fp64; only 64 threads total run this)
// ---------------------------------------------------------------------------
__device__ __forceinline__ double softplusd(double x) {
    // matches jax.nn.softplus = logaddexp(x, 0)
    if (x > 0.0) return x + log1p(exp(-x));
    return log1p(exp(x));
}

// Exact replication of LAPACK SLAEV2 (as used by ssyevd/ssteqr for 2x2).
__device__ void slaev2d(double a, double b, double c,
                        double& rt1, double& rt2, double& cs1, double& sn1) {
    double sm = a + c, df = a - c, adf = fabs(df), tb = b + b, ab = fabs(tb);
    double acmx, acmn;
    if (fabs(a) > fabs(c)) { acmx = a; acmn = c; } else { acmx = c; acmn = a; }
    double rt;
    if (adf > ab)      rt = adf * sqrt(1.0 + (ab / adf) * (ab / adf));
    else if (adf < ab) rt = ab * sqrt(1.0 + (adf / ab) * (adf / ab));
    else               rt = ab * sqrt(2.0);
    int sgn1;
    if (sm < 0.0)      { rt1 = 0.5 * (sm - rt); sgn1 = -1; rt2 = (acmx / rt1) * acmn - (b / rt1) * b; }
    else if (sm > 0.0) { rt1 = 0.5 * (sm + rt); sgn1 = 1;  rt2 = (acmx / rt1) * acmn - (b / rt1) * b; }
    else               { rt1 = 0.5 * rt; rt2 = -0.5 * rt;  sgn1 = 1; }
    int sgn2; double cs;
    if (df >= 0.0) { cs = df + rt; sgn2 = 1; } else { cs = df - rt; sgn2 = -1; }
    double acs = fabs(cs);
    if (acs > ab) {
        double ct = -tb / cs; sn1 = 1.0 / sqrt(1.0 + ct * ct); cs1 = ct * sn1;
    } else {
        if (ab == 0.0) { cs1 = 1.0; sn1 = 0.0; }
        else { double tn = -cs / tb; cs1 = 1.0 / sqrt(1.0 + tn * tn); sn1 = tn * cs1; }
    }
    if (sgn1 == sgn2) { double tau = cs1; cs1 = -sn1; sn1 = tau; }
}

// ---------------------------------------------------------------------------
// Kernel 4: MLP head + per-(b,e) conic geometry. 32 blocks x 256 threads.
// ---------------------------------------------------------------------------
__global__ __launch_bounds__(256) void k_head(
    const float* __restrict__ fc1w, const float* __restrict__ fc1b,
    const float* __restrict__ b1g,  const float* __restrict__ b1b,
    const float* __restrict__ b1m,  const float* __restrict__ b1v,
    const float* __restrict__ fow,  const float* __restrict__ fob,
    const float* __restrict__ Km,   const float* __restrict__ irisR,
    float* __restrict__ out) {
    int b = blockIdx.x;
    int t = threadIdx.x;

    __shared__ float sp[HID];
    __shared__ float sh[HID];
    __shared__ float sraw[OUTD];

    sp[t] = g_p[b * CC + t];
    __syncthreads();

    // hdd[t] = relu(bn(p . fc1_w[t,:] + fc1_b[t]))
    {
        const float4* wr = reinterpret_cast<const float4*>(fc1w + t * CC);
        float a0 = 0.f, a1 = 0.f;
#pragma unroll 8
        for (int i = 0; i < 64; i++) {
            float4 w4 = wr[i];
            a0 = fmaf(w4.x, sp[4 * i + 0], a0);
            a1 = fmaf(w4.y, sp[4 * i + 1], a1);
            a0 = fmaf(w4.z, sp[4 * i + 2], a0);
            a1 = fmaf(w4.w, sp[4 * i + 3], a1);
        }
        float acc = a0 + a1;
        float scale = b1g[t] * rsqrtf(b1v[t] + 1e-5f);
        float hv = fmaxf((acc + fc1b[t] - b1m[t]) * scale + b1b[t], 0.0f);
        sh[t] = hv;
    }
    __syncthreads();

    // raw[o] = hdd . fc_out_w[o,:] + fc_out_b[o]; 14 outputs, 16 threads each
    if (t < 224) {
        int o = t >> 4, g = t & 15;
        float part = 0.f;
#pragma unroll
        for (int i = 0; i < 16; i++)
            part = fmaf(sh[g + 16 * i], fow[o * HID + g + 16 * i], part);
#pragma unroll
        for (int off = 8; off >= 1; off >>= 1)
            part += __shfl_xor_sync(0xffffffffu, part, off, 16);
        if (g == 0) sraw[o] = part + fob[o];
    }
    __syncthreads();

    if (t < 2) {
        int e = t;
        double T[7];
#pragma unroll
        for (int i = 0; i < 7; i++) T[i] = (double)sraw[e * 7 + i];

        double cx = T[0], cy = T[1];
        double ea = softplusd(T[2]) + 1e-6;
        double eb = softplusd(T[3]) + 1e-6;
        double nrm = sqrt(T[4] * T[4] + T[5] * T[5]);
        double cth = T[4] / (nrm + 1e-8), sth = T[5] / (nrm + 1e-8);
        double delta = 0.3 * tanh(T[6]);

        int be = b * 2 + e;
        float* ell = out + (size_t)be * 6;
        ell[0] = (float)cx;  ell[1] = (float)cy;
        ell[2] = (float)ea;  ell[3] = (float)eb;
        ell[4] = (float)cth; ell[5] = (float)sth;

        double theta = atan2(sth, cth);
        double ct = cos(theta), st = sin(theta);
        double ia2 = 1.0 / (ea * ea), ib2 = 1.0 / (eb * eb);
        double A11 = ct * ct * ia2 + st * st * ib2;
        double A22 = st * st * ia2 + ct * ct * ib2;
        double A12 = ct * st * (ia2 - ib2);
        double axv = A11 * cx + A12 * cy;
        double ayv = A12 * cx + A22 * cy;
        double cAc = A11 * cx * cx + 2.0 * A12 * cx * cy + A22 * cy * cy;

        double Cm[3][3] = {{A11, A12, -axv}, {A12, A22, -ayv}, {-axv, -ayv, cAc - 1.0}};
        double Kd[3][3];
#pragma unroll
        for (int r = 0; r < 3; r++)
#pragma unroll
            for (int cc2 = 0; cc2 < 3; cc2++) Kd[r][cc2] = (double)Km[b * 9 + r * 3 + cc2];

        double Tm[3][3], Cn[3][3];
#pragma unroll
        for (int j = 0; j < 3; j++)
#pragma unroll
            for (int l = 0; l < 3; l++)
                Tm[j][l] = Cm[j][0] * Kd[0][l] + Cm[j][1] * Kd[1][l] + Cm[j][2] * Kd[2][l];
#pragma unroll
        for (int i = 0; i < 3; i++)
#pragma unroll
            for (int l = 0; l < 3; l++)
                Cn[i][l] = Kd[0][i] * Tm[0][l] + Kd[1][i] * Tm[1][l] + Kd[2][i] * Tm[2][l];

        double A00 = Cn[0][0], A01 = Cn[0][1], A10 = Cn[1][0], A11n = Cn[1][1];
        double u0 = Cn[0][2], u1 = Cn[1][2];

        double det = A00 * A11n - A01 * A10;
        double mu0 = (-u0 * A11n + A01 * u1) / det;
        double mu1 = (A10 * u0 - A00 * u1) / det;

        // eigh(A) with jax symmetrize + LAPACK ssteqr/slaev2 convention:
        // evals ascending = [rt2, rt1]; evecs[:,0] = (-sn1, cs1)
        double bsym = 0.5 * (A01 + A10);
        double rt1, rt2, cs1, sn1;
        slaev2d(A00, bsym, A11n, rt1, rt2, cs1, sn1);

        double a_n = 1.0 / sqrt(fmax(rt2, 1e-12));
        double b_n = 1.0 / sqrt(fmax(rt1, 1e-12));
        double vx = -sn1, vy = cs1;
        double theta_n = atan2(vy, vx);
        a_n = fmax(a_n, 1e-6);

        double R = (double)irisR[b];
        double z = fmin(fmax(R / a_n, 0.5), 1000.0);

        double rn = sqrt(mu0 * mu0 + mu1 * mu1 + 1.0) + 1e-8;
        double ix = (mu0 / rn) * z, iy = (mu1 / rn) * z, iz = (1.0 / rn) * z;

        double ratio = fmin(fmax(b_n / a_n, 0.0), 1.0);
        double tilt = acos(ratio);
        double ctl = cos(tilt), stl = sin(tilt);
        double kx = cos(theta_n) / (1.0 + 1e-8);
        double ky = sin(theta_n) / (1.0 + 1e-8);
        // kdv = k.z_axis = 0 exactly (k_z == 0)
        double nx = ky * stl, ny = -kx * stl, nz = ctl;
        double nn = sqrt(nx * nx + ny * ny + nz * nz) + 1e-8;
        nx /= nn; ny /= nn; nz /= nn;

        double px = ix + delta * nx, py = iy + delta * ny, pz = iz + delta * nz;

        out[384 + be] = (float)delta;
        float* ic = out + 448 + (size_t)be * 3;
        ic[0] = (float)ix; ic[1] = (float)iy; ic[2] = (float)iz;
        float* no = out + 640 + (size_t)be * 3;
        no[0] = (float)nx; no[1] = (float)ny; no[2] = (float)nz;
        float* pc = out + 832 + (size_t)be * 3;
        pc[0] = (float)px; pc[1] = (float)py; pc[2] = (float)pz;
        out[1024 + be] = (float)z;
    }
}

// ---------------------------------------------------------------------------
extern "C" void kernel_launch(void* const* d_in, const int* in_sizes, int n_in,
                              void* d_out, int out_size) {
    const float* x     = (const float*)d_in[0];
    const float* Kmat  = (const float*)d_in[1];
    const float* irisR = (const float*)d_in[2];
    const float* ca_w1 = (const float*)d_in[3];
    const float* ca_g  = (const float*)d_in[4];
    const float* ca_b  = (const float*)d_in[5];
    const float* ca_m  = (const float*)d_in[6];
    const float* ca_v  = (const float*)d_in[7];
    const float* ca_wh = (const float*)d_in[8];
    const float* ca_ww = (const float*)d_in[9];
    const float* fc1_w = (const float*)d_in[10];
    const float* fc1_b = (const float*)d_in[11];
    const float* bn1_g = (const float*)d_in[12];
    const float* bn1_b = (const float*)d_in[13];
    const float* bn1_m = (const float*)d_in[14];
    const float* bn1_v = (const float*)d_in[15];
    const float* fo_w  = (const float*)d_in[16];
    const float* fo_b  = (const float*)d_in[17];
    float* outp = (float*)d_out;

    k_pool<<<BB * CC, 128>>>(x);
    k_y<<<BB, 128>>>(ca_w1, ca_g, ca_b, ca_m, ca_v);
    k_wpool<<<BB * CC, 128>>>(x, ca_wh, ca_ww);
    k_head<<<BB, 256>>>(fc1_w, fc1_b, bn1_g, bn1_b, bn1_m, bn1_v,
                        fo_w, fo_b, Kmat, irisR, outp);
}

// round 5
// speedup vs baseline: 1.2126x; 1.2126x over previous
#include <cuda_runtime.h>
#include <math.h>

#define BB   32
#define CC   256
#define HH   64
#define WWID 64
#define MIP  8
#define HID  256
#define OUTD 14

// Scratch (no allocations allowed)
__device__ float g_pool[BB * CC * 128];   // per (b,c): [0:64]=row means (xh), [64:128]=col means (xw)
__device__ float g_y[BB * MIP * 128];     // hswish(bn(ca_w1 @ pooled))
__device__ float g_p[BB * CC];            // gated pooled features

// ---------------------------------------------------------------------------
// Kernel 1: per-(b,c) 64x64 tile -> row means + col means. Fully coalesced.
// ---------------------------------------------------------------------------
__global__ __launch_bounds__(128) void k_pool(const float* __restrict__ x) {
    int bid = blockIdx.x;
    int t = threadIdx.x;
    const float4* xp = reinterpret_cast<const float4*>(x) + (size_t)bid * 1024;

    float4 v[8];
#pragma unroll
    for (int k = 0; k < 8; k++) v[k] = xp[k * 128 + t];

    int sub = t >> 4;        // 0..7
    int lane16 = t & 15;     // 0..15

    __shared__ float srow[64];
    __shared__ float scol[8][64];

    float c0 = 0.f, c1 = 0.f, c2 = 0.f, c3 = 0.f;
#pragma unroll
    for (int k = 0; k < 8; k++) {
        float rp = v[k].x + v[k].y + v[k].z + v[k].w;
#pragma unroll
        for (int off = 8; off >= 1; off >>= 1)
            rp += __shfl_xor_sync(0xffffffffu, rp, off, 16);
        if (lane16 == 0) srow[k * 8 + sub] = rp;
        c0 += v[k].x; c1 += v[k].y; c2 += v[k].z; c3 += v[k].w;
    }
    scol[sub][lane16 * 4 + 0] = c0;
    scol[sub][lane16 * 4 + 1] = c1;
    scol[sub][lane16 * 4 + 2] = c2;
    scol[sub][lane16 * 4 + 3] = c3;
    __syncthreads();

    if (t < 64) {
        float cs = 0.f;
#pragma unroll
        for (int r = 0; r < 8; r++) cs += scol[r][t];
        float* outp = g_pool + (size_t)bid * 128;
        outp[t]      = srow[t] * (1.0f / 64.0f);   // xh[h]
        outp[64 + t] = cs      * (1.0f / 64.0f);   // xw[w]
    }
}

// ---------------------------------------------------------------------------
// Kernel 2: y[b,m,l] = hswish(bn(sum_c ca_w1[m,c] * pool[b,c,l])). 32 blocks.
// ---------------------------------------------------------------------------
__global__ __launch_bounds__(128) void k_y(
    const float* __restrict__ w1, const float* __restrict__ bg,
    const float* __restrict__ bb, const float* __restrict__ bm,
    const float* __restrict__ bv) {
    int b = blockIdx.x;
    int t = threadIdx.x;   // t = l (0..127)
    __shared__ float sw1[MIP][CC];
#pragma unroll
    for (int m = 0; m < MIP; m++) {
        sw1[m][t]       = w1[m * CC + t];
        sw1[m][t + 128] = w1[m * CC + t + 128];
    }
    __syncthreads();

    const float* pb = g_pool + (size_t)b * CC * 128;
    float acc[MIP];
#pragma unroll
    for (int m = 0; m < MIP; m++) acc[m] = 0.f;

    for (int c = 0; c < CC; c++) {
        float val = pb[c * 128 + t];
#pragma unroll
        for (int m = 0; m < MIP; m++) acc[m] = fmaf(sw1[m][c], val, acc[m]);
    }
#pragma unroll
    for (int m = 0; m < MIP; m++) {
        float scale = bg[m] * rsqrtf(bv[m] + 1e-5f);
        float yv = (acc[m] - bm[m]) * scale + bb[m];
        float hs = yv * fminf(fmaxf(yv + 3.0f, 0.0f), 6.0f) * (1.0f / 6.0f);
        g_y[(b * MIP + m) * 128 + t] = hs;
    }
}

// ---------------------------------------------------------------------------
// Kernel 3: gated pooling. One block per (b,c).
// ---------------------------------------------------------------------------
__global__ __launch_bounds__(128) void k_wpool(
    const float* __restrict__ x, const float* __restrict__ wh,
    const float* __restrict__ ww) {
    int bid = blockIdx.x;
    int t = threadIdx.x;
    int b = bid >> 8;
    int c = bid & 255;

    const float4* xp = reinterpret_cast<const float4*>(x) + (size_t)bid * 1024;
    float4 v[8];
#pragma unroll
    for (int k = 0; k < 8; k++) v[k] = xp[k * 128 + t];

    __shared__ float sah[64];
    __shared__ float saw[64];
    const float* yb = g_y + (size_t)b * MIP * 128;

    if (t < 64) {
        float s = 0.f;
#pragma unroll
        for (int m = 0; m < MIP; m++) s = fmaf(wh[c * MIP + m], yb[m * 128 + t], s);
        sah[t] = 1.0f / (1.0f + expf(-s));
    } else {
        int w = t - 64;
        float s = 0.f;
#pragma unroll
        for (int m = 0; m < MIP; m++) s = fmaf(ww[c * MIP + m], yb[m * 128 + 64 + w], s);
        saw[w] = 1.0f / (1.0f + expf(-s));
    }
    __syncthreads();

    int sub = t >> 4, lane16 = t & 15, w0 = lane16 * 4;
    float acc = 0.f;
#pragma unroll
    for (int k = 0; k < 8; k++) {
        int h = k * 8 + sub;
        float rs = v[k].x * saw[w0] + v[k].y * saw[w0 + 1] +
                   v[k].z * saw[w0 + 2] + v[k].w * saw[w0 + 3];
        acc = fmaf(sah[h], rs, acc);
    }
#pragma unroll
    for (int off = 16; off >= 1; off >>= 1)
        acc += __shfl_xor_sync(0xffffffffu, acc, off);
    __shared__ float swr[4];
    if ((t & 31) == 0) swr[t >> 5] = acc;
    __syncthreads();
    if (t == 0) g_p[bid] = (swr[0] + swr[1] + swr[2] + swr[3]) * (1.0f / 4096.0f);
}

// ---------------------------------------------------------------------------
// fp32 softplus matching jax.nn.softplus = logaddexp(x, 0)
// ---------------------------------------------------------------------------
__device__ __forceinline__ float softplusf(float x) {
    if (x > 0.0f) return x + log1pf(expf(-x));
    return log1pf(expf(x));
}

// Exact replication of LAPACK SLAEV2 structure (double; non-transcendental).
__device__ void slaev2d(double a, double b, double c,
                        double& rt1, double& rt2, double& cs1, double& sn1) {
    double sm = a + c, df = a - c, adf = fabs(df), tb = b + b, ab = fabs(tb);
    double acmx, acmn;
    if (fabs(a) > fabs(c)) { acmx = a; acmn = c; } else { acmx = c; acmn = a; }
    double rt;
    if (adf > ab)      rt = adf * sqrt(1.0 + (ab / adf) * (ab / adf));
    else if (adf < ab) rt = ab * sqrt(1.0 + (adf / ab) * (adf / ab));
    else               rt = ab * sqrt(2.0);
    int sgn1;
    if (sm < 0.0)      { rt1 = 0.5 * (sm - rt); sgn1 = -1; rt2 = (acmx / rt1) * acmn - (b / rt1) * b; }
    else if (sm > 0.0) { rt1 = 0.5 * (sm + rt); sgn1 = 1;  rt2 = (acmx / rt1) * acmn - (b / rt1) * b; }
    else               { rt1 = 0.5 * rt; rt2 = -0.5 * rt;  sgn1 = 1; }
    int sgn2; double cs;
    if (df >= 0.0) { cs = df + rt; sgn2 = 1; } else { cs = df - rt; sgn2 = -1; }
    double acs = fabs(cs);
    if (acs > ab) {
        double ct = -tb / cs; sn1 = 1.0 / sqrt(1.0 + ct * ct); cs1 = ct * sn1;
    } else {
        if (ab == 0.0) { cs1 = 1.0; sn1 = 0.0; }
        else { double tn = -cs / tb; cs1 = 1.0 / sqrt(1.0 + tn * tn); sn1 = tn * cs1; }
    }
    if (sgn1 == sgn2) { double tau = cs1; cs1 = -sn1; sn1 = tau; }
}

// ---------------------------------------------------------------------------
// Kernel 4: MLP head + per-(b,e) conic geometry.
// All transcendentals eliminated algebraically or done in fp32 MUFU;
// conic congruence + solve + eig kept in fp64 (DFMA-only, short chain).
// ---------------------------------------------------------------------------
__global__ __launch_bounds__(256) void k_head(
    const float* __restrict__ fc1w, const float* __restrict__ fc1b,
    const float* __restrict__ b1g,  const float* __restrict__ b1b,
    const float* __restrict__ b1m,  const float* __restrict__ b1v,
    const float* __restrict__ fow,  const float* __restrict__ fob,
    const float* __restrict__ Km,   const float* __restrict__ irisR,
    float* __restrict__ out) {
    int b = blockIdx.x;
    int t = threadIdx.x;

    __shared__ float sp[HID];
    __shared__ float sh[HID];
    __shared__ float sraw[OUTD];

    sp[t] = g_p[b * CC + t];
    __syncthreads();

    {
        const float4* wr = reinterpret_cast<const float4*>(fc1w + t * CC);
        float a0 = 0.f, a1 = 0.f;
#pragma unroll 8
        for (int i = 0; i < 64; i++) {
            float4 w4 = wr[i];
            a0 = fmaf(w4.x, sp[4 * i + 0], a0);
            a1 = fmaf(w4.y, sp[4 * i + 1], a1);
            a0 = fmaf(w4.z, sp[4 * i + 2], a0);
            a1 = fmaf(w4.w, sp[4 * i + 3], a1);
        }
        float acc = a0 + a1;
        float scale = b1g[t] * rsqrtf(b1v[t] + 1e-5f);
        float hv = fmaxf((acc + fc1b[t] - b1m[t]) * scale + b1b[t], 0.0f);
        sh[t] = hv;
    }
    __syncthreads();

    if (t < 224) {
        int o = t >> 4, g = t & 15;
        float part = 0.f;
#pragma unroll
        for (int i = 0; i < 16; i++)
            part = fmaf(sh[g + 16 * i], fow[o * HID + g + 16 * i], part);
#pragma unroll
        for (int off = 8; off >= 1; off >>= 1)
            part += __shfl_xor_sync(0xffffffffu, part, off, 16);
        if (g == 0) sraw[o] = part + fob[o];
    }
    __syncthreads();

    if (t < 2) {
        int e = t;
        float T0 = sraw[e * 7 + 0], T1 = sraw[e * 7 + 1], T2 = sraw[e * 7 + 2];
        float T3 = sraw[e * 7 + 3], T4 = sraw[e * 7 + 4], T5 = sraw[e * 7 + 5];
        float T6 = sraw[e * 7 + 6];

        float cxf = T0, cyf = T1;
        float eaf = softplusf(T2) + 1e-6f;
        float ebf = softplusf(T3) + 1e-6f;
        float nrm = sqrtf(T4 * T4 + T5 * T5);
        float cth = T4 / (nrm + 1e-8f), sth = T5 / (nrm + 1e-8f);
        float delta = 0.3f * tanhf(T6);

        int be = b * 2 + e;
        float* ell = out + (size_t)be * 6;
        ell[0] = cxf; ell[1] = cyf; ell[2] = eaf; ell[3] = ebf;
        ell[4] = cth; ell[5] = sth;

        // ct,st = cos,sin(atan2(sth,cth)) == renormalized (cth,sth)
        float hyp = sqrtf(cth * cth + sth * sth);
        float ctf = cth / hyp, stf = sth / hyp;

        // ---- conic congruence + solve + eig in double (no transcendentals)
        double cx = (double)cxf, cy = (double)cyf;
        double ct = (double)ctf, st = (double)stf;
        double ia2 = 1.0 / ((double)eaf * (double)eaf);
        double ib2 = 1.0 / ((double)ebf * (double)ebf);
        double A11 = ct * ct * ia2 + st * st * ib2;
        double A22 = st * st * ia2 + ct * ct * ib2;
        double A12 = ct * st * (ia2 - ib2);
        double axv = A11 * cx + A12 * cy;
        double ayv = A12 * cx + A22 * cy;
        double cAc = A11 * cx * cx + 2.0 * A12 * cx * cy + A22 * cy * cy;

        double Cm[3][3] = {{A11, A12, -axv}, {A12, A22, -ayv}, {-axv, -ayv, cAc - 1.0}};
        double Kd[3][3];
#pragma unroll
        for (int r = 0; r < 3; r++)
#pragma unroll
            for (int cc2 = 0; cc2 < 3; cc2++) Kd[r][cc2] = (double)Km[b * 9 + r * 3 + cc2];

        double Tm[3][3], Cn[3][3];
#pragma unroll
        for (int j = 0; j < 3; j++)
#pragma unroll
            for (int l = 0; l < 3; l++)
                Tm[j][l] = Cm[j][0] * Kd[0][l] + Cm[j][1] * Kd[1][l] + Cm[j][2] * Kd[2][l];
#pragma unroll
        for (int i = 0; i < 3; i++)
#pragma unroll
            for (int l = 0; l < 3; l++)
                Cn[i][l] = Kd[0][i] * Tm[0][l] + Kd[1][i] * Tm[1][l] + Kd[2][i] * Tm[2][l];

        double A00 = Cn[0][0], A01 = Cn[0][1], A10 = Cn[1][0], A11n = Cn[1][1];
        double u0 = Cn[0][2], u1 = Cn[1][2];

        double det = A00 * A11n - A01 * A10;
        double mu0 = (-u0 * A11n + A01 * u1) / det;
        double mu1 = (A10 * u0 - A00 * u1) / det;

        double bsym = 0.5 * (A01 + A10);
        double rt1, rt2, cs1, sn1;
        slaev2d(A00, bsym, A11n, rt1, rt2, cs1, sn1);
        // evals ascending = [rt2, rt1]; evecs[:,0] = (-sn1, cs1)

        // ---- back to fp32
        float a_n = 1.0f / sqrtf(fmaxf((float)rt2, 1e-12f));
        float b_n = 1.0f / sqrtf(fmaxf((float)rt1, 1e-12f));
        float vx = (float)(-sn1), vy = (float)cs1;
        a_n = fmaxf(a_n, 1e-6f);

        float R = irisR[b];
        float z = fminf(fmaxf(R / a_n, 0.5f), 1000.0f);

        float m0 = (float)mu0, m1 = (float)mu1;
        float rn = sqrtf(m0 * m0 + m1 * m1 + 1.0f) + 1e-8f;
        float ix = (m0 / rn) * z, iy = (m1 / rn) * z, iz = (1.0f / rn) * z;

        // kx,ky = cos,sin(theta_n) == renormalized eigenvector; /(1+1e-8) from _safe_norm
        float vh = sqrtf(vx * vx + vy * vy);
        float kx = (vx / vh) / (1.0f + 1e-8f);
        float ky = (vy / vh) / (1.0f + 1e-8f);

        // ctl,stl = cos,sin(acos(ratio))
        float ratio = fminf(fmaxf(b_n / a_n, 0.0f), 1.0f);
        float ctl = ratio;
        float stl = sqrtf(fmaxf(1.0f - ratio * ratio, 0.0f));

        // normal = safe_norm( z_ax*ctl + (k x z_ax)*stl + k*0 )
        float nx = ky * stl, ny = -kx * stl, nz = ctl;
        float nn = sqrtf(nx * nx + ny * ny + nz * nz) + 1e-8f;
        nx /= nn; ny /= nn; nz /= nn;

        float px = ix + delta * nx, py = iy + delta * ny, pz = iz + delta * nz;

        out[384 + be] = delta;
        float* ic = out + 448 + (size_t)be * 3;
        ic[0] = ix; ic[1] = iy; ic[2] = iz;
        float* no = out + 640 + (size_t)be * 3;
        no[0] = nx; no[1] = ny; no[2] = nz;
        float* pc = out + 832 + (size_t)be * 3;
        pc[0] = px; pc[1] = py; pc[2] = pz;
        out[1024 + be] = z;
    }
}

// ---------------------------------------------------------------------------
extern "C" void kernel_launch(void* const* d_in, const int* in_sizes, int n_in,
                              void* d_out, int out_size) {
    const float* x     = (const float*)d_in[0];
    const float* Kmat  = (const float*)d_in[1];
    const float* irisR = (const float*)d_in[2];
    const float* ca_w1 = (const float*)d_in[3];
    const float* ca_g  = (const float*)d_in[4];
    const float* ca_b  = (const float*)d_in[5];
    const float* ca_m  = (const float*)d_in[6];
    const float* ca_v  = (const float*)d_in[7];
    const float* ca_wh = (const float*)d_in[8];
    const float* ca_ww = (const float*)d_in[9];
    const float* fc1_w = (const float*)d_in[10];
    const float* fc1_b = (const float*)d_in[11];
    const float* bn1_g = (const float*)d_in[12];
    const float* bn1_b = (const float*)d_in[13];
    const float* bn1_m = (const float*)d_in[14];
    const float* bn1_v = (const float*)d_in[15];
    const float* fo_w  = (const float*)d_in[16];
    const float* fo_b  = (const float*)d_in[17];
    float* outp = (float*)d_out;

    k_pool<<<BB * CC, 128>>>(x);
    k_y<<<BB, 128>>>(ca_w1, ca_g, ca_b, ca_m, ca_v);
    k_wpool<<<BB * CC, 128>>>(x, ca_wh, ca_ww);
    k_head<<<BB, 256>>>(fc1_w, fc1_b, bn1_g, bn1_b, bn1_m, bn1_v,
                        fo_w, fo_b, Kmat, irisR, outp);
}

// round 10
// speedup vs baseline: 1.2632x; 1.0417x over previous
#include <cuda_runtime.h>
#include <math.h>

#define BB   32
#define CC   256
#define HH   64
#define WWID 64
#define MIP  8
#define HID  256
#define OUTD 14

// Scratch (no allocations allowed)
__device__ float g_pool[BB * CC * 128];   // per (b,c): [0:64]=row means (xh), [64:128]=col means (xw)
__device__ float g_y[BB * MIP * 128];     // hswish(bn(ca_w1 @ pooled))
__device__ float g_p[BB * CC];            // gated pooled features

// ---------------------------------------------------------------------------
// Kernel 1: per-(b,c) 64x64 tile -> row means + col means. Fully coalesced.
// ---------------------------------------------------------------------------
__global__ __launch_bounds__(128) void k_pool(const float* __restrict__ x) {
    int bid = blockIdx.x;
    int t = threadIdx.x;
    const float4* xp = reinterpret_cast<const float4*>(x) + (size_t)bid * 1024;

    float4 v[8];
#pragma unroll
    for (int k = 0; k < 8; k++) v[k] = xp[k * 128 + t];

    int sub = t >> 4;        // 0..7
    int lane16 = t & 15;     // 0..15

    __shared__ float srow[64];
    __shared__ float scol[8][64];

    float c0 = 0.f, c1 = 0.f, c2 = 0.f, c3 = 0.f;
#pragma unroll
    for (int k = 0; k < 8; k++) {
        float rp = v[k].x + v[k].y + v[k].z + v[k].w;
#pragma unroll
        for (int off = 8; off >= 1; off >>= 1)
            rp += __shfl_xor_sync(0xffffffffu, rp, off, 16);
        if (lane16 == 0) srow[k * 8 + sub] = rp;
        c0 += v[k].x; c1 += v[k].y; c2 += v[k].z; c3 += v[k].w;
    }
    scol[sub][lane16 * 4 + 0] = c0;
    scol[sub][lane16 * 4 + 1] = c1;
    scol[sub][lane16 * 4 + 2] = c2;
    scol[sub][lane16 * 4 + 3] = c3;
    __syncthreads();

    if (t < 64) {
        float cs = 0.f;
#pragma unroll
        for (int r = 0; r < 8; r++) cs += scol[r][t];
        float* outp = g_pool + (size_t)bid * 128;
        outp[t]      = srow[t] * (1.0f / 64.0f);   // xh[h]
        outp[64 + t] = cs      * (1.0f / 64.0f);   // xw[w]
    }
}

// ---------------------------------------------------------------------------
// Kernel 2: y[b,m,l] = hswish(bn(sum_c ca_w1[m,c] * pool[b,c,l])). 32 blocks.
// ---------------------------------------------------------------------------
__global__ __launch_bounds__(128) void k_y(
    const float* __restrict__ w1, const float* __restrict__ bg,
    const float* __restrict__ bb, const float* __restrict__ bm,
    const float* __restrict__ bv) {
    int b = blockIdx.x;
    int t = threadIdx.x;   // t = l (0..127)
    __shared__ float sw1[MIP][CC];
#pragma unroll
    for (int m = 0; m < MIP; m++) {
        sw1[m][t]       = w1[m * CC + t];
        sw1[m][t + 128] = w1[m * CC + t + 128];
    }
    __syncthreads();

    const float* pb = g_pool + (size_t)b * CC * 128;
    float acc[MIP];
#pragma unroll
    for (int m = 0; m < MIP; m++) acc[m] = 0.f;

    for (int c = 0; c < CC; c++) {
        float val = pb[c * 128 + t];
#pragma unroll
        for (int m = 0; m < MIP; m++) acc[m] = fmaf(sw1[m][c], val, acc[m]);
    }
#pragma unroll
    for (int m = 0; m < MIP; m++) {
        float scale = bg[m] * rsqrtf(bv[m] + 1e-5f);
        float yv = (acc[m] - bm[m]) * scale + bb[m];
        float hs = yv * fminf(fmaxf(yv + 3.0f, 0.0f), 6.0f) * (1.0f / 6.0f);
        g_y[(b * MIP + m) * 128 + t] = hs;
    }
}

// ---------------------------------------------------------------------------
// Kernel 3: gated pooling. One block per (b,c).
// ---------------------------------------------------------------------------
__global__ __launch_bounds__(128) void k_wpool(
    const float* __restrict__ x, const float* __restrict__ wh,
    const float* __restrict__ ww) {
    int bid = blockIdx.x;
    int t = threadIdx.x;
    int b = bid >> 8;
    int c = bid & 255;

    const float4* xp = reinterpret_cast<const float4*>(x) + (size_t)bid * 1024;
    float4 v[8];
#pragma unroll
    for (int k = 0; k < 8; k++) v[k] = xp[k * 128 + t];

    __shared__ float sah[64];
    __shared__ float saw[64];
    const float* yb = g_y + (size_t)b * MIP * 128;

    if (t < 64) {
        float s = 0.f;
#pragma unroll
        for (int m = 0; m < MIP; m++) s = fmaf(wh[c * MIP + m], yb[m * 128 + t], s);
        sah[t] = 1.0f / (1.0f + expf(-s));
    } else {
        int w = t - 64;
        float s = 0.f;
#pragma unroll
        for (int m = 0; m < MIP; m++) s = fmaf(ww[c * MIP + m], yb[m * 128 + 64 + w], s);
        saw[w] = 1.0f / (1.0f + expf(-s));
    }
    __syncthreads();

    int sub = t >> 4, lane16 = t & 15, w0 = lane16 * 4;
    float acc = 0.f;
#pragma unroll
    for (int k = 0; k < 8; k++) {
        int h = k * 8 + sub;
        float rs = v[k].x * saw[w0] + v[k].y * saw[w0 + 1] +
                   v[k].z * saw[w0 + 2] + v[k].w * saw[w0 + 3];
        acc = fmaf(sah[h], rs, acc);
    }
#pragma unroll
    for (int off = 16; off >= 1; off >>= 1)
        acc += __shfl_xor_sync(0xffffffffu, acc, off);
    __shared__ float swr[4];
    if ((t & 31) == 0) swr[t >> 5] = acc;
    __syncthreads();
    if (t == 0) g_p[bid] = (swr[0] + swr[1] + swr[2] + swr[3]) * (1.0f / 4096.0f);
}

// ---------------------------------------------------------------------------
// fp32 softplus matching jax.nn.softplus = logaddexp(x, 0)
// ---------------------------------------------------------------------------
__device__ __forceinline__ float softplusf(float x) {
    if (x > 0.0f) return x + log1pf(expf(-x));
    return log1pf(expf(x));
}

// LAPACK SLAEV2 (single precision — matches jax float32 eigh path).
__device__ __forceinline__ void slaev2f(float a, float b, float c,
                                        float& rt1, float& rt2,
                                        float& cs1, float& sn1) {
    float sm = a + c, df = a - c, adf = fabsf(df), tb = b + b, ab = fabsf(tb);
    float acmx, acmn;
    if (fabsf(a) > fabsf(c)) { acmx = a; acmn = c; } else { acmx = c; acmn = a; }
    float rt;
    if (adf > ab)      rt = adf * sqrtf(1.0f + (ab / adf) * (ab / adf));
    else if (adf < ab) rt = ab * sqrtf(1.0f + (adf / ab) * (adf / ab));
    else               rt = ab * sqrtf(2.0f);
    int sgn1;
    if (sm < 0.0f)      { rt1 = 0.5f * (sm - rt); sgn1 = -1; rt2 = (acmx / rt1) * acmn - (b / rt1) * b; }
    else if (sm > 0.0f) { rt1 = 0.5f * (sm + rt); sgn1 = 1;  rt2 = (acmx / rt1) * acmn - (b / rt1) * b; }
    else                { rt1 = 0.5f * rt; rt2 = -0.5f * rt; sgn1 = 1; }
    int sgn2; float cs;
    if (df >= 0.0f) { cs = df + rt; sgn2 = 1; } else { cs = df - rt; sgn2 = -1; }
    float acs = fabsf(cs);
    if (acs > ab) {
        float ct = -tb / cs; sn1 = 1.0f / sqrtf(1.0f + ct * ct); cs1 = ct * sn1;
    } else {
        if (ab == 0.0f) { cs1 = 1.0f; sn1 = 0.0f; }
        else { float tn = -cs / tb; cs1 = 1.0f / sqrtf(1.0f + tn * tn); sn1 = tn * cs1; }
    }
    if (sgn1 == sgn2) { float tau = cs1; cs1 = -sn1; sn1 = tau; }
}

// ---------------------------------------------------------------------------
// Kernel 4: MLP head + per-(b,e) conic geometry.
// Congruence + mu-solve in fp64 (FMA + one reciprocal); everything else fp32.
// ---------------------------------------------------------------------------
__global__ __launch_bounds__(256) void k_head(
    const float* __restrict__ fc1w, const float* __restrict__ fc1b,
    const float* __restrict__ b1g,  const float* __restrict__ b1b,
    const float* __restrict__ b1m,  const float* __restrict__ b1v,
    const float* __restrict__ fow,  const float* __restrict__ fob,
    const float* __restrict__ Km,   const float* __restrict__ irisR,
    float* __restrict__ out) {
    int b = blockIdx.x;
    int t = threadIdx.x;

    __shared__ float sp[HID];
    __shared__ float sh[HID];
    __shared__ float sraw[OUTD];

    sp[t] = g_p[b * CC + t];
    __syncthreads();

    {
        const float4* wr = reinterpret_cast<const float4*>(fc1w + t * CC);
        float a0 = 0.f, a1 = 0.f;
#pragma unroll 8
        for (int i = 0; i < 64; i++) {
            float4 w4 = wr[i];
            a0 = fmaf(w4.x, sp[4 * i + 0], a0);
            a1 = fmaf(w4.y, sp[4 * i + 1], a1);
            a0 = fmaf(w4.z, sp[4 * i + 2], a0);
            a1 = fmaf(w4.w, sp[4 * i + 3], a1);
        }
        float acc = a0 + a1;
        float scale = b1g[t] * rsqrtf(b1v[t] + 1e-5f);
        float hv = fmaxf((acc + fc1b[t] - b1m[t]) * scale + b1b[t], 0.0f);
        sh[t] = hv;
    }
    __syncthreads();

    if (t < 224) {
        int o = t >> 4, g = t & 15;
        float part = 0.f;
#pragma unroll
        for (int i = 0; i < 16; i++)
            part = fmaf(sh[g + 16 * i], fow[o * HID + g + 16 * i], part);
#pragma unroll
        for (int off = 8; off >= 1; off >>= 1)
            part += __shfl_xor_sync(0xffffffffu, part, off, 16);
        if (g == 0) sraw[o] = part + fob[o];
    }
    __syncthreads();

    if (t < 2) {
        int e = t;
        float T0 = sraw[e * 7 + 0], T1 = sraw[e * 7 + 1], T2 = sraw[e * 7 + 2];
        float T3 = sraw[e * 7 + 3], T4 = sraw[e * 7 + 4], T5 = sraw[e * 7 + 5];
        float T6 = sraw[e * 7 + 6];

        float cxf = T0, cyf = T1;
        float eaf = softplusf(T2) + 1e-6f;
        float ebf = softplusf(T3) + 1e-6f;
        float nrm = sqrtf(T4 * T4 + T5 * T5);
        float cth = T4 / (nrm + 1e-8f), sth = T5 / (nrm + 1e-8f);
        float delta = 0.3f * tanhf(T6);

        int be = b * 2 + e;
        float* ell = out + (size_t)be * 6;
        ell[0] = cxf; ell[1] = cyf; ell[2] = eaf; ell[3] = ebf;
        ell[4] = cth; ell[5] = sth;

        // ct,st = cos,sin(atan2(sth,cth)) == renormalized (cth,sth)
        float hyp = sqrtf(cth * cth + sth * sth);
        float ctf = cth / hyp, stf = sth / hyp;

        // ---- conic congruence + solve in double (FMA-only + one reciprocal)
        double cx = (double)cxf, cy = (double)cyf;
        double ct = (double)ctf, st = (double)stf;
        double ia2 = 1.0 / ((double)eaf * (double)eaf);
        double ib2 = 1.0 / ((double)ebf * (double)ebf);
        double A11 = ct * ct * ia2 + st * st * ib2;
        double A22 = st * st * ia2 + ct * ct * ib2;
        double A12 = ct * st * (ia2 - ib2);
        double axv = A11 * cx + A12 * cy;
        double ayv = A12 * cx + A22 * cy;
        double cAc = A11 * cx * cx + 2.0 * A12 * cx * cy + A22 * cy * cy;

        double Cm[3][3] = {{A11, A12, -axv}, {A12, A22, -ayv}, {-axv, -ayv, cAc - 1.0}};
        double Kd[3][3];
#pragma unroll
        for (int r = 0; r < 3; r++)
#pragma unroll
            for (int cc2 = 0; cc2 < 3; cc2++) Kd[r][cc2] = (double)Km[b * 9 + r * 3 + cc2];

        double Tm[3][3];
#pragma unroll
        for (int j = 0; j < 3; j++)
#pragma unroll
            for (int l = 0; l < 3; l++)
                Tm[j][l] = Cm[j][0] * Kd[0][l] + Cm[j][1] * Kd[1][l] + Cm[j][2] * Kd[2][l];

        // Only the 2x2 block + third column of Cn are needed.
        double A00  = Kd[0][0] * Tm[0][0] + Kd[1][0] * Tm[1][0] + Kd[2][0] * Tm[2][0];
        double A01  = Kd[0][0] * Tm[0][1] + Kd[1][0] * Tm[1][1] + Kd[2][0] * Tm[2][1];
        double A10  = Kd[0][1] * Tm[0][0] + Kd[1][1] * Tm[1][0] + Kd[2][1] * Tm[2][0];
        double A11n = Kd[0][1] * Tm[0][1] + Kd[1][1] * Tm[1][1] + Kd[2][1] * Tm[2][1];
        double u0   = Kd[0][0] * Tm[0][2] + Kd[1][0] * Tm[1][2] + Kd[2][0] * Tm[2][2];
        double u1   = Kd[0][1] * Tm[0][2] + Kd[1][1] * Tm[1][2] + Kd[2][1] * Tm[2][2];

        double rdet = 1.0 / (A00 * A11n - A01 * A10);   // single fp64 division
        float m0 = (float)((-u0 * A11n + A01 * u1) * rdet);
        float m1 = (float)((A10 * u0 - A00 * u1) * rdet);

        // ---- eig in fp32 (matches reference's single-precision SLAEV2)
        float fa = (float)A00, fc = (float)A11n;
        float fb = (float)(0.5 * (A01 + A10));
        float rt1, rt2, cs1, sn1;
        slaev2f(fa, fb, fc, rt1, rt2, cs1, sn1);
        // evals ascending = [rt2, rt1]; evecs[:,0] = (-sn1, cs1)

        float a_n = 1.0f / sqrtf(fmaxf(rt2, 1e-12f));
        float b_n = 1.0f / sqrtf(fmaxf(rt1, 1e-12f));
        float vx = -sn1, vy = cs1;
        a_n = fmaxf(a_n, 1e-6f);

        float R = irisR[b];
        float z = fminf(fmaxf(R / a_n, 0.5f), 1000.0f);

        float rn = sqrtf(m0 * m0 + m1 * m1 + 1.0f) + 1e-8f;
        float ix = (m0 / rn) * z, iy = (m1 / rn) * z, iz = (1.0f / rn) * z;

        // kx,ky = cos,sin(theta_n) == renormalized eigenvector; /(1+1e-8) from _safe_norm
        float vh = sqrtf(vx * vx + vy * vy);
        float kx = (vx / vh) / (1.0f + 1e-8f);
        float ky = (vy / vh) / (1.0f + 1e-8f);

        // ctl,stl = cos,sin(acos(ratio))
        float ratio = fminf(fmaxf(b_n / a_n, 0.0f), 1.0f);
        float ctl = ratio;
        float stl = sqrtf(fmaxf(1.0f - ratio * ratio, 0.0f));

        // normal = safe_norm( z_ax*ctl + (k x z_ax)*stl + k*0 )
        float nx = ky * stl, ny = -kx * stl, nz = ctl;
        float nn = sqrtf(nx * nx + ny * ny + nz * nz) + 1e-8f;
        nx /= nn; ny /= nn; nz /= nn;

        float px = ix + delta * nx, py = iy + delta * ny, pz = iz + delta * nz;

        out[384 + be] = delta;
        float* ic = out + 448 + (size_t)be * 3;
        ic[0] = ix; ic[1] = iy; ic[2] = iz;
        float* no = out + 640 + (size_t)be * 3;
        no[0] = nx; no[1] = ny; no[2] = nz;
        float* pc = out + 832 + (size_t)be * 3;
        pc[0] = px; pc[1] = py; pc[2] = pz;
        out[1024 + be] = z;
    }
}

// ---------------------------------------------------------------------------
extern "C" void kernel_launch(void* const* d_in, const int* in_sizes, int n_in,
                              void* d_out, int out_size) {
    const float* x     = (const float*)d_in[0];
    const float* Kmat  = (const float*)d_in[1];
    const float* irisR = (const float*)d_in[2];
    const float* ca_w1 = (const float*)d_in[3];
    const float* ca_g  = (const float*)d_in[4];
    const float* ca_b  = (const float*)d_in[5];
    const float* ca_m  = (const float*)d_in[6];
    const float* ca_v  = (const float*)d_in[7];
    const float* ca_wh = (const float*)d_in[8];
    const float* ca_ww = (const float*)d_in[9];
    const float* fc1_w = (const float*)d_in[10];
    const float* fc1_b = (const float*)d_in[11];
    const float* bn1_g = (const float*)d_in[12];
    const float* bn1_b = (const float*)d_in[13];
    const float* bn1_m = (const float*)d_in[14];
    const float* bn1_v = (const float*)d_in[15];
    const float* fo_w  = (const float*)d_in[16];
    const float* fo_b  = (const float*)d_in[17];
    float* outp = (float*)d_out;

    k_pool<<<BB * CC, 128>>>(x);
    k_y<<<BB, 128>>>(ca_w1, ca_g, ca_b, ca_m, ca_v);
    k_wpool<<<BB * CC, 128>>>(x, ca_wh, ca_ww);
    k_head<<<BB, 256>>>(fc1_w, fc1_b, bn1_g, bn1_b, bn1_m, bn1_v,
                        fo_w, fo_b, Kmat, irisR, outp);
}